// round 9
// baseline (speedup 1.0000x reference)
#include <cuda_runtime.h>
#include <cstdint>

#define N_Q 4096
#define NTHREADS 1024
#define CLUSTER 4
#define EVAL_PT_SCORE 0.05f
#define D2_THRESH 25.0f   // 5.0^2
#define NBR_CAP 6
#define OVF 255
#define HCAP 2560         // stripe+halo point capacity (expected ~1150)
#define NBUCK 1024
#define NCELL 1152        // 18 rows * 64 cols
#define NCNT (NBUCK + NCELL)   // 2176 fused counters

// smem: hrec 40960 | bkey 32768 | cs 8708 | ccu 8704 | warpsum 256
//       hidx 5120 | nbr 49152 | stat 4096  => 149,764
#define SMEM_BYTES 149764

__device__ __forceinline__ uint32_t smem_u32(const void* p) {
    uint32_t a;
    asm("{ .reg .u64 t; cvta.to.shared.u64 t, %1; cvt.u32.u64 %0, t; }"
        : "=r"(a) : "l"(p));
    return a;
}
__device__ __forceinline__ uint32_t mapa_rank(uint32_t addr, uint32_t r) {
    uint32_t o;
    asm("mapa.shared::cluster.u32 %0, %1, %2;" : "=r"(o) : "r"(addr), "r"(r));
    return o;
}
__device__ __forceinline__ void st_cl_u8(uint32_t addr, uint32_t v) {
    asm volatile("st.shared::cluster.u8 [%0], %1;" :: "r"(addr), "r"(v) : "memory");
}
#define CLUSTER_SYNC() do { \
    asm volatile("barrier.cluster.arrive.aligned;" ::: "memory"); \
    asm volatile("barrier.cluster.wait.aligned;" ::: "memory"); } while (0)

__device__ __forceinline__ int warp_incl_scan(int v) {
    int lane = threadIdx.x & 31;
    #pragma unroll
    for (int o = 1; o < 32; o <<= 1) {
        int n = __shfl_up_sync(0xffffffffu, v, o);
        if (lane >= o) v += n;
    }
    return v;
}

__device__ __forceinline__ unsigned long long mk_key(float s, int i) {
    bool valid = (s >= EVAL_PT_SCORE);
    unsigned int fb = __float_as_uint(s);
    return valid
        ? ((((unsigned long long)fb) << 32) | (unsigned int)(N_Q - 1 - i))
        : (unsigned long long)(unsigned int)(N_Q - 1 - i);
}

__global__ void __launch_bounds__(NTHREADS, 1) __cluster_dims__(CLUSTER, 1, 1)
nms_kernel(const float* __restrict__ logits,
           const float* __restrict__ boxes,
           const float* __restrict__ ts,
           float* __restrict__ out) {
    const int cls = blockIdx.x / CLUSTER;     // 0 = end, 1 = junction
    const int rank = blockIdx.x & (CLUSTER - 1);
    const int tid = threadIdx.x;
    const int lane = tid & 31;
    const int wid = tid >> 5;
    const int rbase = 16 * rank - 1;          // stripe-local row 0 = cell row rbase

    extern __shared__ unsigned char sm[];
    uint4* hrec = (uint4*)sm;                                      // [HCAP]
    unsigned long long* bkey = (unsigned long long*)(hrec + HCAP); // [N_Q] bucket-ordered keys
    int* cs  = (int*)(bkey + N_Q);                                 // [NCNT+1]
    int* ccu = cs + (NCNT + 1);                                    // [NCNT]
    int* warpsum = ccu + NCNT;                                     // [64]
    unsigned short* hidx = (unsigned short*)(warpsum + 64);        // [HCAP]
    unsigned short* nbr  = hidx + HCAP;                            // [NTHREADS*4*NBR_CAP]
    unsigned char* stat  = (unsigned char*)(nbr + NTHREADS * 4 * NBR_CAP); // [N_Q]
    volatile unsigned char* vstat = (volatile unsigned char*)stat;

    const float tw = ts[0], th = ts[1];

    // ---- zero fused counters ----
    for (int c = tid; c < NCNT + 1; c += NTHREADS) cs[c] = 0;
    __syncthreads();

    // ---- phase A: duplicated fast softmax over ALL 4096 (blocked, vector LDG) ----
    unsigned long long rkey[4];
    float rx[4], ry[4];
    int rb[4], rlc[4];
    {
        const float2* lg2 = (const float2*)(logits + 12 * tid);
        float2 L0 = lg2[0], L1 = lg2[1], L2 = lg2[2];
        float2 L3 = lg2[3], L4 = lg2[4], L5 = lg2[5];
        float lg[12] = {L0.x, L0.y, L1.x, L1.y, L2.x, L2.y,
                        L3.x, L3.y, L4.x, L4.y, L5.x, L5.y};
        const float4* bx4 = (const float4*)(boxes + 8 * tid);
        float4 B0 = bx4[0], B1 = bx4[1];
        float bx[8] = {B0.x, B0.y, B0.z, B0.w, B1.x, B1.y, B1.z, B1.w};
        bool own = ((tid >> 8) == rank);       // my 256-thread slab = my index quarter
        #pragma unroll
        for (int k = 0; k < 4; k++) {
            int j = 4 * tid + k;
            float l0 = lg[3 * k], l1 = lg[3 * k + 1], l2 = lg[3 * k + 2];
            float m = fmaxf(l0, fmaxf(l1, l2));
            float e0 = __expf(l0 - m), e1 = __expf(l1 - m), e2 = __expf(l2 - m);
            float inv = __fdividef(1.0f, e0 + e1 + e2);
            float p0 = e0 * inv, p1 = e1 * inv, p2 = e2 * inv;
            float x = bx[2 * k] * tw;
            float y = bx[2 * k + 1] * th;
            float s = (cls == 0) ? p0 : p1;
            bool valid = (s >= EVAL_PT_SCORE);
            unsigned long long key = mk_key(s, j);
            rkey[k] = key; rx[k] = x; ry[k] = y;
            stat[j] = valid ? (unsigned char)0 : (unsigned char)2;
            rb[k] = min(NBUCK - 1, (int)(s * (float)NBUCK));
            if (valid) atomicAdd(&cs[rb[k]], 1);
            int cx = min(63, max(0, (int)(x * 0.125f)));
            int cy = min(63, max(0, (int)(y * 0.125f)));
            int lr = cy - rbase;
            rlc[k] = (lr >= 0 && lr < 18) ? (lr * 64 + cx) : -1;
            if (rlc[k] >= 0) atomicAdd(&cs[NBUCK + rlc[k]], 1);
            if (own) {
                if (cls == 0) {
                    out[5 * j + 0] = 1.0f - p2;
                    out[5 * j + 1] = x;
                    out[5 * j + 2] = y;
                    out[5 * j + 3] = 0.0f;
                } else {
                    out[5 * j + 4] = 0.0f;
                }
            }
        }
    }
    __syncthreads();

    // ---- single fused exclusive scan over 2176 counters (3/thread) ----
    {
        int i0 = 3 * tid, i1 = i0 + 1, i2 = i0 + 2;
        int v0 = (i0 < NCNT) ? cs[i0] : 0;
        int v1 = (i1 < NCNT) ? cs[i1] : 0;
        int v2 = (i2 < NCNT) ? cs[i2] : 0;
        int l = v0 + v1 + v2;
        int il = warp_incl_scan(l);
        if (lane == 31) warpsum[wid] = il;
        __syncthreads();
        if (wid == 0) warpsum[lane] = warp_incl_scan(warpsum[lane]);
        __syncthreads();
        int base = il - l + (wid ? warpsum[wid - 1] : 0);
        if (i0 < NCNT) { cs[i0] = base;            ccu[i0] = base; }
        if (i1 < NCNT) { cs[i1] = base + v0;       ccu[i1] = base + v0; }
        if (i2 < NCNT) { cs[i2] = base + v0 + v1;  ccu[i2] = base + v0 + v1; }
        if (tid == 0) cs[NCNT] = warpsum[31];
    }
    __syncthreads();
    const int nv = cs[NBUCK];            // total valid points

    // ---- scatter: bucket-ordered keys + stripe records ----
    #pragma unroll
    for (int k = 0; k < 4; k++) {
        int j = 4 * tid + k;
        if (rkey[k] >> 32) {
            int bp = atomicAdd(&ccu[rb[k]], 1);
            bkey[bp] = rkey[k];
        }
        if (rlc[k] >= 0) {
            int pos = atomicAdd(&ccu[NBUCK + rlc[k]], 1) - nv;
            hrec[pos] = make_uint4((unsigned int)rkey[k],
                                   (unsigned int)(rkey[k] >> 32),
                                   __float_as_uint(rx[k]),
                                   __float_as_uint(ry[k]));
            hidx[pos] = (unsigned short)j;
        }
    }
    __syncthreads();

    // every CTA's stat[] fully initialized before any remote push lands
    CLUSTER_SYNC();

    #define PUSH_STAT(i, lr, v) do {                                          \
        if ((lr) == 1 && rank > 0)                                            \
            st_cl_u8(mapa_rank(smem_u32(&stat[i]), rank - 1), (v));           \
        if ((lr) == 16 && rank < CLUSTER - 1)                                 \
            st_cl_u8(mapa_rank(smem_u32(&stat[i]), rank + 1), (v));           \
    } while (0)

    // rank-and-write for a retained point (key kj, bucket b, score s)
    #define EMIT(kj, b, skf) do {                                             \
        int rpos = nv - cs[(b) + 1];                                          \
        int qe = cs[(b) + 1];                                                 \
        for (int q = cs[b]; q < qe; q++)                                      \
            if (bkey[q] > (kj)) rpos++;                                       \
        out[5 * rpos + 3 + cls] = (skf);                                      \
    } while (0)

    // ---- fused edge-build + dataflow resolve + output for MY 4 points ----
    {
        int pendmask = 0;
        int cnts[4];
        const int nb_base = tid * (4 * NBR_CAP);
        #pragma unroll
        for (int k = 0; k < 4; k++) {
            int lr = (rlc[k] >= 0) ? (rlc[k] >> 6) : -1;
            if (!(rkey[k] >> 32) || lr < 1 || lr > 16) continue;  // invalid or not owned
            int j = 4 * tid + k;
            unsigned long long kj = rkey[k];
            float xj = rx[k], yj = ry[k];
            int cx = rlc[k] & 63;
            int x0 = max(cx - 1, 0), x1 = min(cx + 1, 63);
            int cnt = 0;
            #pragma unroll
            for (int rr = lr - 1; rr <= lr + 1; rr++) {
                int qs = cs[NBUCK + rr * 64 + x0] - nv;
                int qe = cs[NBUCK + rr * 64 + x1 + 1] - nv;
                for (int q = qs; q < qe; q++) {
                    uint4 C = hrec[q];
                    unsigned long long ki = ((unsigned long long)C.y << 32) | C.x;
                    if (ki <= kj) continue;       // lower rank / invalid / self
                    float dx = __uint_as_float(C.z) - xj;
                    float dy = __uint_as_float(C.w) - yj;
                    if (dx * dx + dy * dy < D2_THRESH) {
                        if (cnt < NBR_CAP) nbr[nb_base + k * NBR_CAP + cnt] = hidx[q];
                        cnt++;
                    }
                }
            }
            if (cnt == 0) {
                stat[j] = 1;
                PUSH_STAT(j, lr, 1u);
                EMIT(kj, rb[k], __uint_as_float((unsigned int)(kj >> 32)));
            } else {
                cnts[k] = (cnt > NBR_CAP) ? OVF : cnt;
                pendmask |= (1 << k);
            }
        }
        // non-blocking round-robin poll of pending points
        while (pendmask) {
            #pragma unroll
            for (int k = 0; k < 4; k++) {
                if (!(pendmask & (1 << k))) continue;
                int j = 4 * tid + k;
                int c = cnts[k];
                bool sup = false, pend = false;
                if (c != OVF) {
                    #pragma unroll
                    for (int i = 0; i < NBR_CAP; i++) {
                        if (i < c) {
                            unsigned char st = vstat[nbr[nb_base + k * NBR_CAP + i]];
                            if (st == 1) sup = true;
                            else if (st == 0) pend = true;
                        }
                    }
                } else {
                    unsigned long long kj = rkey[k];
                    float xj = rx[k], yj = ry[k];
                    int cx = rlc[k] & 63, lr = rlc[k] >> 6;
                    int x0 = max(cx - 1, 0), x1 = min(cx + 1, 63);
                    for (int rr = lr - 1; rr <= lr + 1 && !sup; rr++) {
                        int qs = cs[NBUCK + rr * 64 + x0] - nv;
                        int qe = cs[NBUCK + rr * 64 + x1 + 1] - nv;
                        for (int q = qs; q < qe; q++) {
                            uint4 C = hrec[q];
                            unsigned long long ki = ((unsigned long long)C.y << 32) | C.x;
                            if (ki <= kj) continue;
                            float dx = __uint_as_float(C.z) - xj;
                            float dy = __uint_as_float(C.w) - yj;
                            if (dx * dx + dy * dy < D2_THRESH) {
                                unsigned char st = vstat[hidx[q]];
                                if (st == 1) { sup = true; break; }
                                if (st == 0) pend = true;
                            }
                        }
                    }
                }
                if (sup || !pend) {
                    unsigned int v = sup ? 2u : 1u;
                    int lr = rlc[k] >> 6;
                    vstat[j] = (unsigned char)v;
                    PUSH_STAT(j, lr, v);
                    if (v == 1)
                        EMIT(rkey[k], rb[k],
                             __uint_as_float((unsigned int)(rkey[k] >> 32)));
                    pendmask &= ~(1 << k);
                }
            }
        }
    }

    // keep cluster smem alive until all peers' in-flight pushes land
    CLUSTER_SYNC();
}

extern "C" void kernel_launch(void* const* d_in, const int* in_sizes, int n_in,
                              void* d_out, int out_size) {
    const float* logits = (const float*)d_in[0];   // [1,4096,3]
    const float* boxes  = (const float*)d_in[1];   // [1,4096,2]
    // d_in[2] = pred_gids (unused by reference)
    const float* ts     = (const float*)d_in[3];   // [1,2] = (w,h)
    float* out = (float*)d_out;                    // [1,4096,5]

    cudaFuncSetAttribute(nms_kernel,
                         cudaFuncAttributeMaxDynamicSharedMemorySize, SMEM_BYTES);
    nms_kernel<<<2 * CLUSTER, NTHREADS, SMEM_BYTES>>>(logits, boxes, ts, out);
}

// round 10
// speedup vs baseline: 1.2892x; 1.2892x over previous
#include <cuda_runtime.h>
#include <cstdint>

#define N_Q 4096
#define NTHREADS 1024
#define CLUSTER 4
#define EVAL_PT_SCORE 0.05f
#define D2_THRESH 25.0f   // 5.0^2
#define NBR_CAP 6
#define OVF 255
#define HCAP 2560         // stripe+halo point capacity (expected ~1150)
#define WCAP 2048         // worklist capacity (expected ~460)
#define NBUCK 1024
#define NCELL 1152        // 18 rows * 64 cols
#define NCNT (NBUCK + NCELL)   // 2176 fused counters

// smem: hrec 40960 | bkey 32768 | cs 8708 | ccu 8704 | warpsum 256
//       hidx 5120 | hcell 5120 | wl 4096 | nbr 24576 | stat 4096 | nbrcnt 2048
#define SMEM_BYTES 136452

__device__ __forceinline__ uint32_t smem_u32(const void* p) {
    uint32_t a;
    asm("{ .reg .u64 t; cvta.to.shared.u64 t, %1; cvt.u32.u64 %0, t; }"
        : "=r"(a) : "l"(p));
    return a;
}
__device__ __forceinline__ uint32_t mapa_rank(uint32_t addr, uint32_t r) {
    uint32_t o;
    asm("mapa.shared::cluster.u32 %0, %1, %2;" : "=r"(o) : "r"(addr), "r"(r));
    return o;
}
__device__ __forceinline__ void st_cl_u8(uint32_t addr, uint32_t v) {
    asm volatile("st.shared::cluster.u8 [%0], %1;" :: "r"(addr), "r"(v) : "memory");
}
#define CLUSTER_SYNC() do { \
    asm volatile("barrier.cluster.arrive.aligned;" ::: "memory"); \
    asm volatile("barrier.cluster.wait.aligned;" ::: "memory"); } while (0)

__device__ __forceinline__ int warp_incl_scan(int v) {
    int lane = threadIdx.x & 31;
    #pragma unroll
    for (int o = 1; o < 32; o <<= 1) {
        int n = __shfl_up_sync(0xffffffffu, v, o);
        if (lane >= o) v += n;
    }
    return v;
}

__device__ __forceinline__ unsigned long long mk_key(float s, int i) {
    bool valid = (s >= EVAL_PT_SCORE);
    unsigned int fb = __float_as_uint(s);
    return valid
        ? ((((unsigned long long)fb) << 32) | (unsigned int)(N_Q - 1 - i))
        : (unsigned long long)(unsigned int)(N_Q - 1 - i);
}

__global__ void __launch_bounds__(NTHREADS, 1) __cluster_dims__(CLUSTER, 1, 1)
nms_kernel(const float* __restrict__ logits,
           const float* __restrict__ boxes,
           const float* __restrict__ ts,
           float* __restrict__ out) {
    const int cls = blockIdx.x / CLUSTER;     // 0 = end, 1 = junction
    const int rank = blockIdx.x & (CLUSTER - 1);
    const int tid = threadIdx.x;
    const int lane = tid & 31;
    const int wid = tid >> 5;
    const int rbase = 16 * rank - 1;          // stripe-local row 0 = cell row rbase

    extern __shared__ unsigned char sm[];
    uint4* hrec = (uint4*)sm;                                      // [HCAP]
    unsigned long long* bkey = (unsigned long long*)(hrec + HCAP); // [N_Q] bucket-ordered keys
    int* cs  = (int*)(bkey + N_Q);                                 // [NCNT+1]
    int* ccu = cs + (NCNT + 1);                                    // [NCNT]
    int* warpsum = ccu + NCNT;                                     // [64]
    unsigned short* hidx  = (unsigned short*)(warpsum + 64);       // [HCAP]
    unsigned short* hcell = hidx + HCAP;                           // [HCAP]
    unsigned short* wl    = hcell + HCAP;                          // [WCAP]
    unsigned short* nbr   = wl + WCAP;                             // [WCAP*NBR_CAP]
    unsigned char* stat   = (unsigned char*)(nbr + WCAP * NBR_CAP);// [N_Q]
    unsigned char* nbrcnt = stat + N_Q;                            // [WCAP]
    volatile unsigned char* vstat = (volatile unsigned char*)stat;
    __shared__ int s_wl;

    const float tw = ts[0], th = ts[1];

    // ---- zero fused counters ----
    for (int c = tid; c < NCNT + 1; c += NTHREADS) cs[c] = 0;
    if (tid == 0) s_wl = 0;
    __syncthreads();

    // ---- phase A: duplicated fast softmax over ALL 4096 (blocked, vector LDG) ----
    unsigned long long rkey[4];
    float rx[4], ry[4];
    int rb[4], rlc[4];
    {
        const float2* lg2 = (const float2*)(logits + 12 * tid);
        float2 L0 = lg2[0], L1 = lg2[1], L2 = lg2[2];
        float2 L3 = lg2[3], L4 = lg2[4], L5 = lg2[5];
        float lg[12] = {L0.x, L0.y, L1.x, L1.y, L2.x, L2.y,
                        L3.x, L3.y, L4.x, L4.y, L5.x, L5.y};
        const float4* bx4 = (const float4*)(boxes + 8 * tid);
        float4 B0 = bx4[0], B1 = bx4[1];
        float bx[8] = {B0.x, B0.y, B0.z, B0.w, B1.x, B1.y, B1.z, B1.w};
        bool own = ((tid >> 8) == rank);       // my 256-thread slab = my index quarter
        #pragma unroll
        for (int k = 0; k < 4; k++) {
            int j = 4 * tid + k;
            float l0 = lg[3 * k], l1 = lg[3 * k + 1], l2 = lg[3 * k + 2];
            float m = fmaxf(l0, fmaxf(l1, l2));
            float e0 = __expf(l0 - m), e1 = __expf(l1 - m), e2 = __expf(l2 - m);
            float inv = __fdividef(1.0f, e0 + e1 + e2);
            float p0 = e0 * inv, p1 = e1 * inv, p2 = e2 * inv;
            float x = bx[2 * k] * tw;
            float y = bx[2 * k + 1] * th;
            float s = (cls == 0) ? p0 : p1;
            bool valid = (s >= EVAL_PT_SCORE);
            unsigned long long key = mk_key(s, j);
            rkey[k] = key; rx[k] = x; ry[k] = y;
            stat[j] = valid ? (unsigned char)0 : (unsigned char)2;
            rb[k] = min(NBUCK - 1, (int)(s * (float)NBUCK));
            if (valid) atomicAdd(&cs[rb[k]], 1);
            int cx = min(63, max(0, (int)(x * 0.125f)));
            int cy = min(63, max(0, (int)(y * 0.125f)));
            int lr = cy - rbase;
            rlc[k] = (lr >= 0 && lr < 18) ? (lr * 64 + cx) : -1;
            if (rlc[k] >= 0) atomicAdd(&cs[NBUCK + rlc[k]], 1);
            if (own) {
                if (cls == 0) {
                    out[5 * j + 0] = 1.0f - p2;
                    out[5 * j + 1] = x;
                    out[5 * j + 2] = y;
                    out[5 * j + 3] = 0.0f;
                } else {
                    out[5 * j + 4] = 0.0f;
                }
            }
        }
    }
    __syncthreads();

    // ---- single fused exclusive scan over 2176 counters (3/thread) ----
    {
        int i0 = 3 * tid, i1 = i0 + 1, i2 = i0 + 2;
        int v0 = (i0 < NCNT) ? cs[i0] : 0;
        int v1 = (i1 < NCNT) ? cs[i1] : 0;
        int v2 = (i2 < NCNT) ? cs[i2] : 0;
        int l = v0 + v1 + v2;
        int il = warp_incl_scan(l);
        if (lane == 31) warpsum[wid] = il;
        __syncthreads();
        if (wid == 0) warpsum[lane] = warp_incl_scan(warpsum[lane]);
        __syncthreads();
        int base = il - l + (wid ? warpsum[wid - 1] : 0);
        if (i0 < NCNT) { cs[i0] = base;            ccu[i0] = base; }
        if (i1 < NCNT) { cs[i1] = base + v0;       ccu[i1] = base + v0; }
        if (i2 < NCNT) { cs[i2] = base + v0 + v1;  ccu[i2] = base + v0 + v1; }
        if (tid == 0) cs[NCNT] = warpsum[31];
    }
    __syncthreads();
    const int nv = cs[NBUCK];            // total valid points
    const int htotal = cs[NCNT] - nv;    // stripe+halo points

    // ---- scatter: bucket-ordered keys (valid) + stripe records ----
    #pragma unroll
    for (int k = 0; k < 4; k++) {
        int j = 4 * tid + k;
        if (rkey[k] >> 32) {
            int bp = atomicAdd(&ccu[rb[k]], 1);
            bkey[bp] = rkey[k];
        }
        if (rlc[k] >= 0) {
            int pos = atomicAdd(&ccu[NBUCK + rlc[k]], 1) - nv;
            hrec[pos] = make_uint4((unsigned int)rkey[k],
                                   (unsigned int)(rkey[k] >> 32),
                                   __float_as_uint(rx[k]),
                                   __float_as_uint(ry[k]));
            hidx[pos] = (unsigned short)j;
            hcell[pos] = (unsigned short)rlc[k];
        }
    }
    __syncthreads();

    // every CTA's stat[] fully initialized before any remote push lands
    CLUSTER_SYNC();

    #define PUSH_STAT(i, lr, v) do {                                          \
        if ((lr) == 1 && rank > 0)                                            \
            st_cl_u8(mapa_rank(smem_u32(&stat[i]), rank - 1), (v));           \
        if ((lr) == 16 && rank < CLUSTER - 1)                                 \
            st_cl_u8(mapa_rank(smem_u32(&stat[i]), rank + 1), (v));           \
    } while (0)

    // rank-and-write for a retained point with key kj
    #define EMIT(kj) do {                                                     \
        float sc_ = __uint_as_float((unsigned int)((kj) >> 32));              \
        int b_ = min(NBUCK - 1, (int)(sc_ * (float)NBUCK));                   \
        int rpos_ = nv - cs[b_ + 1];                                          \
        int qe_ = cs[b_ + 1];                                                 \
        for (int q_ = cs[b_]; q_ < qe_; q_++)                                 \
            if (bkey[q_] > (kj)) rpos_++;                                     \
        out[5 * rpos_ + 3 + cls] = sc_;                                       \
    } while (0)

    // ---- edge build for OWNED points (local rows 1..16); cnt==0 emits now ----
    for (int p = tid; p < htotal; p += NTHREADS) {
        uint4 R = hrec[p];
        if (R.y == 0) continue;                   // invalid
        int lc = hcell[p];
        int lr = lc >> 6;
        if (lr < 1 || lr > 16) continue;          // halo-only
        unsigned long long kj = ((unsigned long long)R.y << 32) | R.x;
        float xj = __uint_as_float(R.z), yj = __uint_as_float(R.w);
        int cx = lc & 63;
        int x0 = max(cx - 1, 0), x1 = min(cx + 1, 63);
        unsigned short tmp[NBR_CAP];
        int cnt = 0;
        #pragma unroll
        for (int rr = lr - 1; rr <= lr + 1; rr++) {
            int qs = cs[NBUCK + rr * 64 + x0] - nv;
            int qe = cs[NBUCK + rr * 64 + x1 + 1] - nv;
            for (int q = qs; q < qe; q++) {
                uint4 C = hrec[q];
                unsigned long long ki = ((unsigned long long)C.y << 32) | C.x;
                if (ki <= kj) continue;           // lower rank / invalid / self
                float dx = __uint_as_float(C.z) - xj;
                float dy = __uint_as_float(C.w) - yj;
                if (dx * dx + dy * dy < D2_THRESH) {
                    if (cnt < NBR_CAP) tmp[cnt] = hidx[q];
                    cnt++;
                }
            }
        }
        int i = hidx[p];
        if (cnt == 0) {
            stat[i] = 1;                          // top of its neighborhood
            PUSH_STAT(i, lr, 1u);
            EMIT(kj);
        } else {
            int w = atomicAdd(&s_wl, 1);
            wl[w] = (unsigned short)p;
            nbrcnt[w] = (cnt > NBR_CAP) ? (unsigned char)OVF : (unsigned char)cnt;
            #pragma unroll
            for (int k = 0; k < NBR_CAP; k++)
                if (k < cnt) nbr[w * NBR_CAP + k] = tmp[k];
        }
    }
    __syncthreads();
    const int nwl = s_wl;

    // ---- dataflow resolution on compact worklist; retained emit inline ----
    for (int w = tid; w < nwl; w += NTHREADS) {
        int p = wl[w];
        int i = hidx[p];
        uint4 R = hrec[p];
        unsigned long long kj = ((unsigned long long)R.y << 32) | R.x;
        int lr = hcell[p] >> 6;
        int c = nbrcnt[w];
        unsigned int res = 0;
        if (c != OVF) {
            while (res == 0) {
                bool sup = false, pend = false;
                #pragma unroll 1
                for (int k = 0; k < c; k++) {
                    unsigned char st = vstat[nbr[w * NBR_CAP + k]];
                    if (st == 1) { sup = true; break; }
                    if (st == 0) pend = true;
                }
                if (sup) res = 2;
                else if (!pend) res = 1;
            }
        } else {
            float xj = __uint_as_float(R.z), yj = __uint_as_float(R.w);
            int lc = hcell[p];
            int cx = lc & 63;
            int x0 = max(cx - 1, 0), x1 = min(cx + 1, 63);
            while (res == 0) {
                bool sup = false, pend = false;
                for (int rr = lr - 1; rr <= lr + 1 && !sup; rr++) {
                    int qs = cs[NBUCK + rr * 64 + x0] - nv;
                    int qe = cs[NBUCK + rr * 64 + x1 + 1] - nv;
                    for (int q = qs; q < qe; q++) {
                        uint4 C = hrec[q];
                        unsigned long long ki = ((unsigned long long)C.y << 32) | C.x;
                        if (ki <= kj) continue;
                        float dx = __uint_as_float(C.z) - xj;
                        float dy = __uint_as_float(C.w) - yj;
                        if (dx * dx + dy * dy < D2_THRESH) {
                            unsigned char st = vstat[hidx[q]];
                            if (st == 1) { sup = true; break; }
                            if (st == 0) pend = true;
                        }
                    }
                }
                if (sup) res = 2;
                else if (!pend) res = 1;
            }
        }
        vstat[i] = (unsigned char)res;            // local visibility for spinners
        PUSH_STAT(i, lr, res);                    // remote visibility for neighbor
        if (res == 1) EMIT(kj);
    }

    // keep cluster smem alive until all peers' in-flight pushes land
    CLUSTER_SYNC();
}

extern "C" void kernel_launch(void* const* d_in, const int* in_sizes, int n_in,
                              void* d_out, int out_size) {
    const float* logits = (const float*)d_in[0];   // [1,4096,3]
    const float* boxes  = (const float*)d_in[1];   // [1,4096,2]
    // d_in[2] = pred_gids (unused by reference)
    const float* ts     = (const float*)d_in[3];   // [1,2] = (w,h)
    float* out = (float*)d_out;                    // [1,4096,5]

    cudaFuncSetAttribute(nms_kernel,
                         cudaFuncAttributeMaxDynamicSharedMemorySize, SMEM_BYTES);
    nms_kernel<<<2 * CLUSTER, NTHREADS, SMEM_BYTES>>>(logits, boxes, ts, out);
}

// round 11
// speedup vs baseline: 1.4508x; 1.1254x over previous
#include <cuda_runtime.h>
#include <cstdint>

#define N_Q 4096
#define NTHREADS 1024
#define STRIPES 8
#define EVAL_PT_SCORE 0.05f
#define D2_THRESH 25.0f   // 5.0^2
#define NBR_CAP 6
#define OVF 255
#define HCAP 1536         // 10-row halo region capacity (expected ~640)
#define WCAP 1024
#define NBUCK 1024
#define NCELL 640         // 10 rows * 64 cols
#define NCNT (NBUCK + NCELL)   // 1664 fused counters

// K2 smem carve-out = 96,516 bytes (see pointers below)
#define SMEM_BYTES 96516

// -------- device scratch (per class) --------
__device__ unsigned long long g_key[2][N_Q];
__device__ float2 g_xy[2][N_Q];
__device__ int g_stat[2][N_Q];    // 0=pending 1=retained 2=suppressed/invalid

__device__ __forceinline__ int warp_incl_scan(int v) {
    int lane = threadIdx.x & 31;
    #pragma unroll
    for (int o = 1; o < 32; o <<= 1) {
        int n = __shfl_up_sync(0xffffffffu, v, o);
        if (lane >= o) v += n;
    }
    return v;
}

__device__ __forceinline__ unsigned long long mk_key(float s, int i) {
    bool valid = (s >= EVAL_PT_SCORE);
    unsigned int fb = __float_as_uint(s);
    return valid
        ? ((((unsigned long long)fb) << 32) | (unsigned int)(N_Q - 1 - i))
        : (unsigned long long)(unsigned int)(N_Q - 1 - i);
}

// ---------------- K1: per-point prep, zero duplication ----------------
__global__ void __launch_bounds__(NTHREADS)
prep_kernel(const float* __restrict__ logits,
            const float* __restrict__ boxes,
            const float* __restrict__ ts,
            float* __restrict__ out) {
    int t = blockIdx.x * NTHREADS + threadIdx.x;   // 0..8191
    int cls = t >> 12;
    int j = t & (N_Q - 1);
    float l0 = logits[3 * j + 0];
    float l1 = logits[3 * j + 1];
    float l2 = logits[3 * j + 2];
    float m = fmaxf(l0, fmaxf(l1, l2));
    float e0 = __expf(l0 - m), e1 = __expf(l1 - m), e2 = __expf(l2 - m);
    float inv = __fdividef(1.0f, e0 + e1 + e2);
    float p0 = e0 * inv, p1 = e1 * inv, p2 = e2 * inv;
    float x = boxes[2 * j + 0] * ts[0];
    float y = boxes[2 * j + 1] * ts[1];
    float s = cls ? p1 : p0;
    g_key[cls][j] = mk_key(s, j);
    g_xy[cls][j] = make_float2(x, y);
    g_stat[cls][j] = (s >= EVAL_PT_SCORE) ? 0 : 2;
    if (cls == 0) {
        out[5 * j + 0] = 1.0f - p2;
        out[5 * j + 1] = x;
        out[5 * j + 2] = y;
        out[5 * j + 3] = 0.0f;
    } else {
        out[5 * j + 4] = 0.0f;
    }
}

// ---------------- K2: stripe CSR + edge build + gmem dataflow ----------------
__global__ void __launch_bounds__(NTHREADS, 1)
resolve_kernel(float* __restrict__ out) {
    const int rank = blockIdx.x & (STRIPES - 1);
    const int cls = blockIdx.x >> 3;
    const int tid = threadIdx.x;
    const int lane = tid & 31;
    const int wid = tid >> 5;
    const int rbase = 8 * rank - 1;      // stripe-local row 0 = cell row rbase

    extern __shared__ unsigned char sm[];
    uint4* hrec = (uint4*)sm;                                      // [HCAP]
    unsigned long long* bkey = (unsigned long long*)(hrec + HCAP); // [N_Q]
    int* cs  = (int*)(bkey + N_Q);                                 // [NCNT+1]
    int* ccu = cs + (NCNT + 1);                                    // [NCNT]
    int* warpsum = ccu + NCNT;                                     // [64]
    unsigned short* hidx  = (unsigned short*)(warpsum + 64);       // [HCAP]
    unsigned short* hcell = hidx + HCAP;                           // [HCAP]
    unsigned short* wl    = hcell + HCAP;                          // [WCAP]
    unsigned short* nbr   = wl + WCAP;                             // [WCAP*NBR_CAP]
    unsigned char* lstat  = (unsigned char*)(nbr + WCAP * NBR_CAP);// [N_Q]
    unsigned char* nbrcnt = lstat + N_Q;                           // [WCAP]
    volatile unsigned char* vls = (volatile unsigned char*)lstat;
    volatile int* vg = (volatile int*)g_stat[cls];
    __shared__ int s_wl;

    // ---- zero counters ----
    for (int c = tid; c < NCNT + 1; c += NTHREADS) cs[c] = 0;
    if (tid == 0) s_wl = 0;
    __syncthreads();

    // ---- load precomputed records; histograms ----
    unsigned long long rkey[4];
    float rx[4], ry[4];
    int rb[4], rlc[4];
    #pragma unroll
    for (int k = 0; k < 4; k++) {
        int j = k * NTHREADS + tid;
        unsigned long long key = g_key[cls][j];
        float2 p = g_xy[cls][j];
        rkey[k] = key; rx[k] = p.x; ry[k] = p.y;
        bool valid = (key >> 32) != 0ull;
        lstat[j] = valid ? (unsigned char)0 : (unsigned char)2;
        if (valid) {
            float s = __uint_as_float((unsigned int)(key >> 32));
            rb[k] = min(NBUCK - 1, (int)(s * (float)NBUCK));
            atomicAdd(&cs[rb[k]], 1);
        } else rb[k] = 0;
        int cx = min(63, max(0, (int)(p.x * 0.125f)));
        int cy = min(63, max(0, (int)(p.y * 0.125f)));
        int lr = cy - rbase;
        rlc[k] = (lr >= 0 && lr < 10) ? (lr * 64 + cx) : -1;
        if (rlc[k] >= 0) atomicAdd(&cs[NBUCK + rlc[k]], 1);
    }
    __syncthreads();

    // ---- fused exclusive scan over 1664 counters (2/thread) ----
    {
        int i0 = 2 * tid, i1 = i0 + 1;
        int v0 = (i0 < NCNT) ? cs[i0] : 0;
        int v1 = (i1 < NCNT) ? cs[i1] : 0;
        int l = v0 + v1;
        int il = warp_incl_scan(l);
        if (lane == 31) warpsum[wid] = il;
        __syncthreads();
        if (wid == 0) warpsum[lane] = warp_incl_scan(warpsum[lane]);
        __syncthreads();
        int base = il - l + (wid ? warpsum[wid - 1] : 0);
        if (i0 < NCNT) { cs[i0] = base;       ccu[i0] = base; }
        if (i1 < NCNT) { cs[i1] = base + v0;  ccu[i1] = base + v0; }
        if (tid == 0) cs[NCNT] = warpsum[31];
    }
    __syncthreads();
    const int nv = cs[NBUCK];            // total valid points

    // ---- scatter: bucket-ordered keys + stripe records ----
    #pragma unroll
    for (int k = 0; k < 4; k++) {
        int j = k * NTHREADS + tid;
        if (rkey[k] >> 32) {
            int bp = atomicAdd(&ccu[rb[k]], 1);
            bkey[bp] = rkey[k];
        }
        if (rlc[k] >= 0) {
            int pos = atomicAdd(&ccu[NBUCK + rlc[k]], 1) - nv;
            hrec[pos] = make_uint4((unsigned int)rkey[k],
                                   (unsigned int)(rkey[k] >> 32),
                                   __float_as_uint(rx[k]),
                                   __float_as_uint(ry[k]));
            hidx[pos] = (unsigned short)j;
            hcell[pos] = (unsigned short)rlc[k];
        }
    }
    __syncthreads();

    // rank-and-write for a retained point with key kj
    #define EMIT(kj) do {                                                     \
        float sc_ = __uint_as_float((unsigned int)((kj) >> 32));              \
        int b_ = min(NBUCK - 1, (int)(sc_ * (float)NBUCK));                   \
        int rpos_ = nv - cs[b_ + 1];                                          \
        int qe_ = cs[b_ + 1];                                                 \
        for (int q_ = cs[b_]; q_ < qe_; q_++)                                 \
            if (bkey[q_] > (kj)) rpos_++;                                     \
        out[5 * rpos_ + 3 + cls] = sc_;                                       \
    } while (0)

    // stat of a resolved owned point is published to gmem only from boundary rows
    #define PUBLISH(i, lr, v) do {                                            \
        vls[i] = (unsigned char)(v);                                          \
        if ((lr) == 1 || (lr) == 8) vg[i] = (int)(v);                         \
    } while (0)

    // ---- edge build for OWNED records: rows 1..8 are contiguous in CSR ----
    const int pstart = cs[NBUCK + 64] - nv;        // start of local row 1
    const int pend   = cs[NBUCK + 9 * 64] - nv;    // end of local row 8
    for (int p = pstart + tid; p < pend; p += NTHREADS) {
        uint4 R = hrec[p];
        if (R.y == 0) continue;                    // invalid
        int lc = hcell[p];
        int lr = lc >> 6;                          // 1..8
        unsigned long long kj = ((unsigned long long)R.y << 32) | R.x;
        float xj = __uint_as_float(R.z), yj = __uint_as_float(R.w);
        int cx = lc & 63;
        int x0 = max(cx - 1, 0), x1 = min(cx + 1, 63);
        unsigned short tmp[NBR_CAP];
        int cnt = 0;
        #pragma unroll
        for (int rr = lr - 1; rr <= lr + 1; rr++) {
            unsigned short rem = (rr == 0 || rr == 9) ? 0x8000 : 0;
            int qs = cs[NBUCK + rr * 64 + x0] - nv;
            int qe = cs[NBUCK + rr * 64 + x1 + 1] - nv;
            for (int q = qs; q < qe; q++) {
                uint4 C = hrec[q];
                unsigned long long ki = ((unsigned long long)C.y << 32) | C.x;
                if (ki <= kj) continue;            // lower rank / invalid / self
                float dx = __uint_as_float(C.z) - xj;
                float dy = __uint_as_float(C.w) - yj;
                if (dx * dx + dy * dy < D2_THRESH) {
                    if (cnt < NBR_CAP) tmp[cnt] = hidx[q] | rem;
                    cnt++;
                }
            }
        }
        int i = hidx[p];
        if (cnt == 0) {
            PUBLISH(i, lr, 1u);
            EMIT(kj);
        } else {
            int w = atomicAdd(&s_wl, 1);
            wl[w] = (unsigned short)p;
            nbrcnt[w] = (cnt > NBR_CAP) ? (unsigned char)OVF : (unsigned char)cnt;
            #pragma unroll
            for (int k = 0; k < NBR_CAP; k++)
                if (k < cnt) nbr[w * NBR_CAP + k] = tmp[k];
        }
    }
    __syncthreads();
    const int nwl = s_wl;

    // ---- dataflow resolution: local via smem, cross-stripe via L2 ----
    for (int w = tid; w < nwl; w += NTHREADS) {
        int p = wl[w];
        int i = hidx[p];
        uint4 R = hrec[p];
        unsigned long long kj = ((unsigned long long)R.y << 32) | R.x;
        int lc = hcell[p];
        int lr = lc >> 6;
        int c = nbrcnt[w];
        unsigned int res = 0;
        if (c != OVF) {
            while (res == 0) {
                bool sup = false, pend2 = false;
                #pragma unroll 1
                for (int k = 0; k < c; k++) {
                    unsigned short nb = nbr[w * NBR_CAP + k];
                    int idx = nb & 0x7FFF;
                    int st = (nb & 0x8000) ? vg[idx] : (int)vls[idx];
                    if (st == 1) { sup = true; break; }
                    if (st == 0) pend2 = true;
                }
                if (sup) res = 2;
                else if (!pend2) res = 1;
            }
        } else {
            float xj = __uint_as_float(R.z), yj = __uint_as_float(R.w);
            int cx = lc & 63;
            int x0 = max(cx - 1, 0), x1 = min(cx + 1, 63);
            while (res == 0) {
                bool sup = false, pend2 = false;
                for (int rr = lr - 1; rr <= lr + 1 && !sup; rr++) {
                    bool rem = (rr == 0 || rr == 9);
                    int qs = cs[NBUCK + rr * 64 + x0] - nv;
                    int qe = cs[NBUCK + rr * 64 + x1 + 1] - nv;
                    for (int q = qs; q < qe; q++) {
                        uint4 C = hrec[q];
                        unsigned long long ki = ((unsigned long long)C.y << 32) | C.x;
                        if (ki <= kj) continue;
                        float dx = __uint_as_float(C.z) - xj;
                        float dy = __uint_as_float(C.w) - yj;
                        if (dx * dx + dy * dy < D2_THRESH) {
                            int idx = hidx[q];
                            int st = rem ? vg[idx] : (int)vls[idx];
                            if (st == 1) { sup = true; break; }
                            if (st == 0) pend2 = true;
                        }
                    }
                }
                if (sup) res = 2;
                else if (!pend2) res = 1;
            }
        }
        PUBLISH(i, lr, res);
        if (res == 1) EMIT(kj);
    }
}

extern "C" void kernel_launch(void* const* d_in, const int* in_sizes, int n_in,
                              void* d_out, int out_size) {
    const float* logits = (const float*)d_in[0];   // [1,4096,3]
    const float* boxes  = (const float*)d_in[1];   // [1,4096,2]
    // d_in[2] = pred_gids (unused by reference)
    const float* ts     = (const float*)d_in[3];   // [1,2] = (w,h)
    float* out = (float*)d_out;                    // [1,4096,5]

    prep_kernel<<<2 * N_Q / NTHREADS, NTHREADS>>>(logits, boxes, ts, out);

    cudaFuncSetAttribute(resolve_kernel,
                         cudaFuncAttributeMaxDynamicSharedMemorySize, SMEM_BYTES);
    resolve_kernel<<<2 * STRIPES, NTHREADS, SMEM_BYTES>>>(out);
}